// round 15
// baseline (speedup 1.0000x reference)
#include <cuda_runtime.h>
#include <cuda_fp16.h>
#include <cstdint>

#define BATCH   16384
#define D_DIM   768
#define H_DIM   256
#define NQ      8
#define NL      2

// ---------------- scratch -----------------------------------------------------
__device__ float2 g_C[NL][NQ][4];

__device__ __align__(256) float  g_h[BATCH * H_DIM];
__device__ __align__(256) __half g_xf[BATCH * D_DIM];
__device__ __align__(256) __half g_w1f[D_DIM * H_DIM];
__device__ __align__(256) __half g_w4f[H_DIM * D_DIM];
__device__ __align__(256) __half g_ef[BATCH * H_DIM];

// ---------------- helpers ------------------------------------------------------
__device__ __forceinline__ float2 cmul(float2 a, float2 b) {
    return make_float2(a.x * b.x - a.y * b.y, a.x * b.y + a.y * b.x);
}
__device__ __forceinline__ float2 cadd(float2 a, float2 b) {
    return make_float2(a.x + b.x, a.y + b.y);
}
__device__ __forceinline__ float gelu_exact(float v) {
    return 0.5f * v * (1.0f + erff(v * 0.70710678118654752f));
}
__device__ __forceinline__ uint32_t smem_to_u32(const void* p) {
    uint32_t a;
    asm("{ .reg .u64 t; cvta.to.shared.u64 t, %1; cvt.u32.u64 %0, t; }"
        : "=r"(a) : "l"(p));
    return a;
}
__device__ __forceinline__ uint2 cvt4_f16(float4 v) {
    __half2 p0 = __floats2half2_rn(v.x, v.y);
    __half2 p1 = __floats2half2_rn(v.z, v.w);
    uint2 o;
    o.x = *reinterpret_cast<uint32_t*>(&p0);
    o.y = *reinterpret_cast<uint32_t*>(&p1);
    return o;
}
__device__ __forceinline__ float2 shfl2(float2 v, int mask) {
    v.x = __shfl_xor_sync(0xffffffffu, v.x, mask);
    v.y = __shfl_xor_sync(0xffffffffu, v.y, mask);
    return v;
}

__device__ __forceinline__ void ldsm_x4(uint32_t addr, uint32_t* r) {
    asm volatile("ldmatrix.sync.aligned.m8n8.x4.shared.b16 {%0,%1,%2,%3}, [%4];"
        : "=r"(r[0]), "=r"(r[1]), "=r"(r[2]), "=r"(r[3]) : "r"(addr));
}
__device__ __forceinline__ void ldsm_x4t(uint32_t addr, uint32_t* r) {
    asm volatile("ldmatrix.sync.aligned.m8n8.x4.trans.shared.b16 {%0,%1,%2,%3}, [%4];"
        : "=r"(r[0]), "=r"(r[1]), "=r"(r[2]), "=r"(r[3]) : "r"(addr));
}
__device__ __forceinline__ void mma16816(float* d, const uint32_t* a,
                                         uint32_t b0, uint32_t b1) {
    asm volatile(
        "mma.sync.aligned.m16n8k16.row.col.f32.f16.f16.f32 "
        "{%0,%1,%2,%3}, {%4,%5,%6,%7}, {%8,%9}, {%0,%1,%2,%3};"
        : "+f"(d[0]), "+f"(d[1]), "+f"(d[2]), "+f"(d[3])
        : "r"(a[0]), "r"(a[1]), "r"(a[2]), "r"(a[3]), "r"(b0), "r"(b1));
}
__device__ __forceinline__ void cp16(uint32_t saddr, const void* g) {
    asm volatile("cp.async.cg.shared.global [%0], [%1], 16;"
        :: "r"(saddr), "l"(g) : "memory");
}
#define CP_COMMIT() asm volatile("cp.async.commit_group;" ::: "memory")
#define CP_WAIT(n)  asm volatile("cp.async.wait_group %0;" :: "n"(n) : "memory")

// ---------------- prep: gates + weight conv (small, runs first) ---------------
#define WB  ((2 * (D_DIM * H_DIM / 4) + 255) / 256)     // 384

__global__ __launch_bounds__(256) void prep_gw(
    const float* __restrict__ qw,
    const float4* __restrict__ w14, const float4* __restrict__ w44,
    uint2* __restrict__ w1f, uint2* __restrict__ w4f)
{
    int b = blockIdx.x;
    int tid = threadIdx.x;
    if (b == 0) {
        if (tid >= NL * NQ) return;
        int l = tid / NQ, i = tid % NQ;
        float w0 = qw[(l * NQ + i) * 3 + 0];
        float w1 = qw[(l * NQ + i) * 3 + 1];
        float w2 = qw[(l * NQ + i) * 3 + 2];
        float c0 = cosf(0.5f * w0), s0 = sinf(0.5f * w0);
        float c1 = cosf(0.5f * w1), s1 = sinf(0.5f * w1);
        float c2 = cosf(0.5f * w2), s2 = sinf(0.5f * w2);
        float2 e0  = make_float2(c0, -s0);
        float2 e0c = make_float2(c0,  s0);
        float2 T00 = make_float2( c1 * e0.x,   c1 * e0.y);
        float2 T01 = make_float2(-s1 * e0c.x, -s1 * e0c.y);
        float2 T10 = make_float2( s1 * e0.x,   s1 * e0.y);
        float2 T11 = make_float2( c1 * e0c.x,  c1 * e0c.y);
        float2 e2  = make_float2(c2, -s2);
        float2 e2c = make_float2(c2,  s2);
        g_C[l][i][0] = cmul(e2,  T00);
        g_C[l][i][1] = cmul(e2,  T01);
        g_C[l][i][2] = cmul(e2c, T10);
        g_C[l][i][3] = cmul(e2c, T11);
    } else {
        int i = (b - 1) * 256 + tid;
        int nw4 = D_DIM * H_DIM / 4;
        if (i >= 2 * nw4) return;
        if (i < nw4) w1f[i] = cvt4_f16(w14[i]);
        else         w4f[i - nw4] = cvt4_f16(w44[i - nw4]);
    }
}

// per-half x conversion
__global__ __launch_bounds__(256) void conv_x(
    const float4* __restrict__ src, uint2* __restrict__ dst, int n4)
{
    int i = blockIdx.x * 256 + threadIdx.x;
    if (i >= n4) return;
    dst[i] = cvt4_f16(src[i]);
}

// ---------------- GEMM-1: h = gelu(x@W1+b1), fp16 MMA, 6-stage ---------------
#define STAGES 6
#define STAGE_BYTES 16384
#define SM_TOT (STAGES * STAGE_BYTES)    // 98304, 2 CTAs/SM = 192 KB

__global__ __launch_bounds__(256, 2) void gemm_gelu(
    const float* __restrict__ bias, int N, int K, int brow0)
{
    extern __shared__ char smem[];
    const __half* Af = g_xf;
    const __half* Bf = g_w1f;
    float* Cout = g_h;

    uint32_t sb = smem_to_u32(smem);
    int t = threadIdx.x, wid = t >> 5, lane = t & 31;
    int brow = brow0 + blockIdx.y * 128, bcol = blockIdx.x * 128;
    int warpM = (wid & 3) * 32, warpN = (wid >> 2) * 64;
    int grp = lane >> 2, qc = lane & 3;

    float acc[2][8][4];
#pragma unroll
    for (int i = 0; i < 2; ++i)
#pragma unroll
        for (int j = 0; j < 8; ++j)
#pragma unroll
            for (int k = 0; k < 4; ++k) acc[i][j][k] = 0.f;

    int NC = K / 32;
    int a_row0 = t >> 2, a_kseg = t & 3;
    int b_kr0  = t >> 4, b_nseg = t & 15;

    uint32_t aoff[2], boff[4];
#pragma unroll
    for (int mf = 0; mf < 2; ++mf) {
        int m = warpM + mf * 16 + (lane & 15);
        aoff[mf] = (uint32_t)((m * 64 + (lane >> 4) * 16) ^ ((m & 7) << 4));
    }
#pragma unroll
    for (int n16 = 0; n16 < 4; ++n16) {
        uint32_t nb = (uint32_t)(warpN + n16 * 16 + (lane >> 4) * 8) * 2;
        boff[n16] = (uint32_t)((lane & 15) * 256) + (nb ^ (uint32_t)((lane & 7) << 4));
    }

    auto issue_stage = [&](int ck, int stg) {
        uint32_t base = sb + stg * STAGE_BYTES;
        int k0 = ck * 32;
#pragma unroll
        for (int i = 0; i < 2; ++i) {
            int row = a_row0 + i * 64;
            uint32_t off = (uint32_t)((row * 64 + a_kseg * 16) ^ ((row & 7) << 4));
            cp16(base + off, Af + (size_t)(brow + row) * K + k0 + a_kseg * 8);
        }
#pragma unroll
        for (int i = 0; i < 2; ++i) {
            int kr = b_kr0 + i * 16;
            uint32_t off = (uint32_t)((kr * 256 + b_nseg * 16) ^ ((kr & 7) << 4));
            cp16(base + 8192 + off, Bf + (size_t)(k0 + kr) * N + bcol + b_nseg * 8);
        }
    };

#pragma unroll
    for (int p = 0; p < STAGES - 1; ++p) {
        if (p < NC) issue_stage(p, p);
        CP_COMMIT();
    }

    for (int ck = 0; ck < NC; ++ck) {
        CP_WAIT(STAGES - 2);
        __syncthreads();

        int nx = ck + STAGES - 1;
        if (nx < NC) issue_stage(nx, nx % STAGES);
        CP_COMMIT();

        uint32_t base = sb + (uint32_t)((ck % STAGES) * STAGE_BYTES);
        uint32_t bbase = base + 8192;

#pragma unroll
        for (int s = 0; s < 2; ++s) {
            uint32_t sa = (uint32_t)(s << 5);
            uint32_t sbo = (uint32_t)(s * 4096);
            uint32_t ah[2][4];
#pragma unroll
            for (int mf = 0; mf < 2; ++mf)
                ldsm_x4(base + (aoff[mf] ^ sa), ah[mf]);
#pragma unroll
            for (int n16 = 0; n16 < 4; ++n16) {
                uint32_t bh[4];
                ldsm_x4t(bbase + boff[n16] + sbo, bh);
#pragma unroll
                for (int half = 0; half < 2; ++half) {
                    int nf = n16 * 2 + half;
#pragma unroll
                    for (int mf = 0; mf < 2; ++mf)
                        mma16816(acc[mf][nf], ah[mf], bh[half * 2], bh[half * 2 + 1]);
                }
            }
        }
    }

#pragma unroll
    for (int mf = 0; mf < 2; ++mf) {
        int r0 = brow + warpM + mf * 16 + grp;
#pragma unroll
        for (int nf = 0; nf < 8; ++nf) {
            int col = bcol + warpN + nf * 8 + qc * 2;
            float bv0 = bias[col], bv1 = bias[col + 1];
            float v0 = gelu_exact(acc[mf][nf][0] + bv0);
            float v1 = gelu_exact(acc[mf][nf][1] + bv1);
            float v2 = gelu_exact(acc[mf][nf][2] + bv0);
            float v3 = gelu_exact(acc[mf][nf][3] + bv1);
            size_t o0 = (size_t)r0 * N + col;
            size_t o1 = o0 + (size_t)8 * N;
            *(float2*)(Cout + o0) = make_float2(v0, v1);
            *(float2*)(Cout + o1) = make_float2(v2, v3);
        }
    }
}

// ---------------- GEMM-2 fused: out = LN(x + e@W4 + b4), 4-stage -------------
#define LSTAGES 4
#define LA_BYTES 2048
#define LB_BYTES 49152
#define LSTAGE_BYTES (LA_BYTES + LB_BYTES)
#define SM_TOT2 (LSTAGES * LSTAGE_BYTES)    // 204800

__global__ __launch_bounds__(512, 1) void gemm_resid_ln(
    const float* __restrict__ bias, const float* __restrict__ resid,
    const float* __restrict__ gamma, const float* __restrict__ beta,
    float* __restrict__ out, int row0)
{
    extern __shared__ char smem[];
    const __half* Af = g_ef;
    const __half* Bf = g_w4f;
    const int N = D_DIM, K = H_DIM;

    uint32_t sb = smem_to_u32(smem);
    int t = threadIdx.x, wid = t >> 5, lane = t & 31;
    int brow = row0 + blockIdx.x * 32;
    int grp = lane >> 2, qc = lane & 3;

    float acc[2][6][4];
#pragma unroll
    for (int i = 0; i < 2; ++i)
#pragma unroll
        for (int j = 0; j < 6; ++j)
#pragma unroll
            for (int k = 0; k < 4; ++k) acc[i][j][k] = 0.f;

    const int NC = K / 32;

    int a_row = t >> 2, a_kseg = t & 3;
    int b_kr = t >> 4, b_nc0 = t & 15;

    uint32_t aoff[2], boff[3];
#pragma unroll
    for (int mf = 0; mf < 2; ++mf) {
        int m = mf * 16 + (lane & 15);
        aoff[mf] = (uint32_t)((m * 64 + (lane >> 4) * 16) ^ ((m & 7) << 4));
    }
#pragma unroll
    for (int n16 = 0; n16 < 3; ++n16) {
        uint32_t nb = (uint32_t)(wid * 48 + n16 * 16 + (lane >> 4) * 8) * 2;
        boff[n16] = (uint32_t)((lane & 15) * 1536) + (nb ^ (uint32_t)((lane & 7) << 4));
    }

    auto issue_stage = [&](int ck, int stg) {
        uint32_t base = sb + stg * LSTAGE_BYTES;
        int k0 = ck * 32;
        if (t < 128) {
            uint32_t off = (uint32_t)((a_row * 64 + a_kseg * 16) ^ ((a_row & 7) << 4));
            cp16(base + off, Af + (size_t)(brow + a_row) * K + k0 + a_kseg * 8);
        }
        uint32_t bb = base + LA_BYTES;
#pragma unroll
        for (int i = 0; i < 6; ++i) {
            int nc = b_nc0 + i * 16;
            uint32_t off = (uint32_t)(b_kr * 1536 + ((nc * 16) ^ ((b_kr & 7) << 4)));
            cp16(bb + off, Bf + (size_t)(k0 + b_kr) * N + nc * 8);
        }
    };

#pragma unroll
    for (int p = 0; p < LSTAGES - 1; ++p) {
        if (p < NC) issue_stage(p, p);
        CP_COMMIT();
    }

    for (int ck = 0; ck < NC; ++ck) {
        CP_WAIT(LSTAGES - 2);
        __syncthreads();

        int nx = ck + LSTAGES - 1;
        if (nx < NC) issue_stage(nx, nx % LSTAGES);
        CP_COMMIT();

        uint32_t base = sb + (uint32_t)((ck % LSTAGES) * LSTAGE_BYTES);
        uint32_t bbase = base + LA_BYTES;

#pragma unroll
        for (int s = 0; s < 2; ++s) {
            uint32_t sa = (uint32_t)(s << 5);
            uint32_t sbo = (uint32_t)(s * 16 * 1536);
            uint32_t ah[2][4];
#pragma unroll
            for (int mf = 0; mf < 2; ++mf)
                ldsm_x4(base + (aoff[mf] ^ sa), ah[mf]);
#pragma unroll
            for (int n16 = 0; n16 < 3; ++n16) {
                uint32_t bh[4];
                ldsm_x4t(bbase + boff[n16] + sbo, bh);
#pragma unroll
                for (int half = 0; half < 2; ++half) {
                    int nf = n16 * 2 + half;
#pragma unroll
                    for (int mf = 0; mf < 2; ++mf)
                        mma16816(acc[mf][nf], ah[mf], bh[half * 2], bh[half * 2 + 1]);
                }
            }
        }
    }

    // ---- epilogue: stage acc+bias to smem, then per-row coalesced LN ----
    CP_WAIT(0);
    __syncthreads();
    float* ys = (float*)smem;    // [32][768] fp32 = 96 KB

#pragma unroll
    for (int mf = 0; mf < 2; ++mf) {
        int r0 = mf * 16 + grp;
#pragma unroll
        for (int nf = 0; nf < 6; ++nf) {
            int col = wid * 48 + nf * 8 + qc * 2;
            float2 bv = *(const float2*)(bias + col);
            ys[r0 * D_DIM + col]           = acc[mf][nf][0] + bv.x;
            ys[r0 * D_DIM + col + 1]       = acc[mf][nf][1] + bv.y;
            ys[(r0 + 8) * D_DIM + col]     = acc[mf][nf][2] + bv.x;
            ys[(r0 + 8) * D_DIM + col + 1] = acc[mf][nf][3] + bv.y;
        }
    }
    __syncthreads();

#pragma unroll
    for (int rr = 0; rr < 2; ++rr) {
        int lrow = wid * 2 + rr;
        size_t grow = (size_t)(brow + lrow) * D_DIM;
        float y[24];
        float sum = 0.f, sq = 0.f;
#pragma unroll
        for (int i = 0; i < 6; ++i) {
            int col = lane * 4 + i * 128;
            float4 s4 = *(const float4*)(ys + lrow * D_DIM + col);
            float4 r4 = *(const float4*)(resid + grow + col);
            float y0 = s4.x + r4.x, y1 = s4.y + r4.y;
            float y2 = s4.z + r4.z, y3 = s4.w + r4.w;
            y[4 * i + 0] = y0; y[4 * i + 1] = y1;
            y[4 * i + 2] = y2; y[4 * i + 3] = y3;
            sum += y0 + y1 + y2 + y3;
            sq  += y0 * y0 + y1 * y1 + y2 * y2 + y3 * y3;
        }
#pragma unroll
        for (int o = 16; o; o >>= 1) {
            sum += __shfl_xor_sync(0xffffffffu, sum, o);
            sq  += __shfl_xor_sync(0xffffffffu, sq,  o);
        }
        float mu  = sum * (1.0f / D_DIM);
        float var = sq * (1.0f / D_DIM) - mu * mu;
        float inv = rsqrtf(var + 1e-5f);
#pragma unroll
        for (int i = 0; i < 6; ++i) {
            int col = lane * 4 + i * 128;
            float4 gm = *(const float4*)(gamma + col);
            float4 bt = *(const float4*)(beta + col);
            float4 o4;
            o4.x = gm.x * (y[4 * i + 0] - mu) * inv + bt.x;
            o4.y = gm.y * (y[4 * i + 1] - mu) * inv + bt.y;
            o4.z = gm.z * (y[4 * i + 2] - mu) * inv + bt.z;
            o4.w = gm.w * (y[4 * i + 3] - mu) * inv + bt.w;
            *(float4*)(out + grow + col) = o4;
        }
    }
}

// ---------------- quantum bottleneck ------------------------------------------
template <int M_, int H_>
__device__ __forceinline__ void apply_gate(float2* amp, int lane,
    const float2* Cw, float c, float s)
{
    float2 C00 = Cw[0], C01 = Cw[1], C10 = Cw[2], C11 = Cw[3];
    float2 U00 = make_float2(C00.x * c + C01.x * s, C00.y * c + C01.y * s);
    float2 U01 = make_float2(C01.x * c - C00.x * s, C01.y * c - C00.y * s);
    float2 U10 = make_float2(C10.x * c + C11.x * s, C10.y * c + C11.y * s);
    float2 U11 = make_float2(C11.x * c - C10.x * s, C11.y * c - C10.y * s);

    constexpr int mreg  = (M_ >> 5) & 7;
    constexpr int mlane = M_ & 31;
    constexpr int hreg  = (H_ >> 5) & 7;
    constexpr int hlane = H_ & 31;
    bool lp = (__popc(lane & hlane) & 1) != 0;
    if (mreg == 0) {
#pragma unroll
        for (int r = 0; r < 8; ++r) {
            bool hi = lp ^ ((__popc(r & hreg) & 1) != 0);
            float2 o = shfl2(amp[r], mlane);
            float2 lo_v = cadd(cmul(U00, amp[r]), cmul(U01, o));
            float2 hi_v = cadd(cmul(U10, o), cmul(U11, amp[r]));
            amp[r] = hi ? hi_v : lo_v;
        }
    } else {
#pragma unroll
        for (int r = 0; r < 8; ++r) {
            int pr = r ^ mreg;
            if (r < pr) {
                float2 a = amp[r], b = amp[pr];
                float2 ash = (mlane != 0) ? shfl2(a, mlane) : a;
                float2 bsh = (mlane != 0) ? shfl2(b, mlane) : b;
                bool hi_r  = lp ^ ((__popc(r  & hreg) & 1) != 0);
                bool hi_pr = lp ^ ((__popc(pr & hreg) & 1) != 0);
                amp[r]  = hi_r  ? cadd(cmul(U10, bsh), cmul(U11, a))
                                : cadd(cmul(U00, a),   cmul(U01, bsh));
                amp[pr] = hi_pr ? cadd(cmul(U10, ash), cmul(U11, b))
                                : cadd(cmul(U00, b),   cmul(U01, ash));
            }
        }
    }
}

#define QWARPS 8
__global__ __launch_bounds__(QWARPS * 32) void quantum_kernel(
    const float* __restrict__ W2, const float* __restrict__ b2,
    const float* __restrict__ W3, const float* __restrict__ b3,
    int row0)
{
    int warp = threadIdx.x >> 5;
    int lane = threadIdx.x & 31;
    int row  = row0 + blockIdx.x * QWARPS + warp;

    const float* hrow = g_h + (size_t)row * H_DIM;
    float fj[8] = {0, 0, 0, 0, 0, 0, 0, 0};
#pragma unroll
    for (int m = 0; m < 8; ++m) {
        int k = lane + 32 * m;
        float hv = hrow[k];
        const float4* w2p = (const float4*)(W2 + (size_t)k * 8);
        float4 wa = w2p[0], wb = w2p[1];
        fj[0] += hv * wa.x; fj[1] += hv * wa.y;
        fj[2] += hv * wa.z; fj[3] += hv * wa.w;
        fj[4] += hv * wb.x; fj[5] += hv * wb.y;
        fj[6] += hv * wb.z; fj[7] += hv * wb.w;
    }
#pragma unroll
    for (int j = 0; j < 8; ++j)
#pragma unroll
        for (int o = 16; o; o >>= 1)
            fj[j] += __shfl_xor_sync(0xffffffffu, fj[j], o);

    float cf[8], sf[8];
#pragma unroll
    for (int j = 0; j < 8; ++j) {
        float f = 0.5f * (fj[j] + b2[j]);
        sincosf(f, &sf[j], &cf[j]);
    }

    auto vsel = [&](int w, bool b) -> float2 {
        float2 Ca = g_C[0][w][b ? 2 : 0];
        float2 Cb = g_C[0][w][b ? 3 : 1];
        return make_float2(Ca.x * cf[w] + Cb.x * sf[w], Ca.y * cf[w] + Cb.y * sf[w]);
    };
    float2 pl = vsel(3, (lane & 16) != 0);
    pl = cmul(pl, vsel(4, (lane & 8) != 0));
    pl = cmul(pl, vsel(5, (lane & 4) != 0));
    pl = cmul(pl, vsel(6, (lane & 2) != 0));
    pl = cmul(pl, vsel(7, (lane & 1) != 0));

    float2 amp[8];
    {
        float2 a0 = vsel(0, false), a1 = vsel(0, true);
        float2 b0 = vsel(1, false), b1 = vsel(1, true);
        float2 c0 = vsel(2, false), c1 = vsel(2, true);
        float2 p00 = cmul(a0, b0), p01v = cmul(a0, b1);
        float2 p10 = cmul(a1, b0), p11 = cmul(a1, b1);
        amp[0] = cmul(cmul(p00, c0), pl);
        amp[1] = cmul(cmul(p00, c1), pl);
        amp[2] = cmul(cmul(p01v, c0), pl);
        amp[3] = cmul(cmul(p01v, c1), pl);
        amp[4] = cmul(cmul(p10, c0), pl);
        amp[5] = cmul(cmul(p10, c1), pl);
        amp[6] = cmul(cmul(p11, c0), pl);
        amp[7] = cmul(cmul(p11, c1), pl);
    }

    apply_gate<0xC0, 0x7F>(amp, lane, g_C[1][0], cf[0], sf[0]);
    apply_gate<0x60, 0xC0>(amp, lane, g_C[1][1], cf[1], sf[1]);
    apply_gate<0x30, 0xE0>(amp, lane, g_C[1][2], cf[2], sf[2]);
    apply_gate<0x18, 0xF0>(amp, lane, g_C[1][3], cf[3], sf[3]);
    apply_gate<0x0C, 0xF8>(amp, lane, g_C[1][4], cf[4], sf[4]);
    apply_gate<0x06, 0xFC>(amp, lane, g_C[1][5], cf[5], sf[5]);
    apply_gate<0x03, 0xFE>(amp, lane, g_C[1][6], cf[6], sf[6]);
    apply_gate<0xC1, 0xFF>(amp, lane, g_C[1][7], cf[7], sf[7]);

    const int measm[8] = {0xD5, 0xBF, 0x5F, 0xAF, 0x57, 0xAB, 0x55, 0xAA};
    float zf[8] = {0, 0, 0, 0, 0, 0, 0, 0};
#pragma unroll
    for (int r = 0; r < 8; ++r) {
        float p = amp[r].x * amp[r].x + amp[r].y * amp[r].y;
#pragma unroll
        for (int i = 0; i < 8; ++i) {
            bool neg = ((__popc(lane & (measm[i] & 31)) ^ __popc(r & (measm[i] >> 5))) & 1) != 0;
            zf[i] += neg ? -p : p;
        }
    }
#pragma unroll
    for (int j = 0; j < 8; ++j)
#pragma unroll
        for (int o = 16; o; o >>= 1)
            zf[j] += __shfl_xor_sync(0xffffffffu, zf[j], o);

    size_t ebase = (size_t)row * H_DIM;
#pragma unroll
    for (int m = 0; m < 8; ++m) {
        int k = lane + 32 * m;
        float acc = b3[k];
#pragma unroll
        for (int j = 0; j < 8; ++j) acc += zf[j] * W3[j * H_DIM + k];
        g_ef[ebase + k] = __float2half(gelu_exact(acc));
    }
}

// ---------------- launch ------------------------------------------------------
extern "C" void kernel_launch(void* const* d_in, const int* in_sizes, int n_in,
                              void* d_out, int out_size) {
    const float* x     = (const float*)d_in[0];
    const float* W1    = (const float*)d_in[1];
    const float* b1    = (const float*)d_in[2];
    const float* W2    = (const float*)d_in[3];
    const float* b2    = (const float*)d_in[4];
    const float* qw    = (const float*)d_in[5];
    const float* W3    = (const float*)d_in[6];
    const float* b3    = (const float*)d_in[7];
    const float* W4    = (const float*)d_in[8];
    const float* b4    = (const float*)d_in[9];
    const float* gamma = (const float*)d_in[10];
    const float* beta  = (const float*)d_in[11];
    float* out = (float*)d_out;

    int Brows = in_sizes[0] / D_DIM;   // 16384
    int half  = Brows / 2;

    static cudaStream_t s1 = nullptr;
    static cudaEvent_t evW = nullptr, evB = nullptr;
    if (!s1) {
        cudaStreamCreateWithFlags(&s1, cudaStreamNonBlocking);
        cudaEventCreateWithFlags(&evW, cudaEventDisableTiming);
        cudaEventCreateWithFlags(&evB, cudaEventDisableTiming);
        cudaFuncSetAttribute(gemm_gelu, cudaFuncAttributeMaxDynamicSharedMemorySize, SM_TOT);
        cudaFuncSetAttribute(gemm_resid_ln, cudaFuncAttributeMaxDynamicSharedMemorySize, SM_TOT2);
    }

    void *pxf, *pw1f, *pw4f;
    cudaGetSymbolAddress(&pxf, g_xf);
    cudaGetSymbolAddress(&pw1f, g_w1f);
    cudaGetSymbolAddress(&pw4f, g_w4f);

    // gates + weights (small) on default stream; fork after it
    prep_gw<<<1 + WB, 256>>>(
        qw, (const float4*)W1, (const float4*)W4, (uint2*)pw1f, (uint2*)pw4f);
    cudaEventRecord(evW, 0);
    cudaStreamWaitEvent(s1, evW, 0);

    int nh4 = (half * D_DIM) / 4;   // float4 per half

    dim3 gG(H_DIM / 128, half / 128);   // (2, 64) per half
    int  gQ = half / QWARPS;            // 1024
    int  gF = half / 32;                // 256

    // chain A (rows [0, half)) on default stream
    conv_x<<<(nh4 + 255) / 256, 256>>>((const float4*)x, (uint2*)pxf, nh4);
    gemm_gelu<<<gG, 256, SM_TOT>>>(b1, H_DIM, D_DIM, 0);
    quantum_kernel<<<gQ, QWARPS * 32>>>(W2, b2, W3, b3, 0);
    gemm_resid_ln<<<gF, 512, SM_TOT2>>>(b4, x, gamma, beta, out, 0);

    // chain B (rows [half, Brows)) on s1
    conv_x<<<(nh4 + 255) / 256, 256, 0, s1>>>(
        (const float4*)(x + (size_t)half * D_DIM),
        (uint2*)((__half*)pxf + (size_t)half * D_DIM), nh4);
    gemm_gelu<<<gG, 256, SM_TOT, s1>>>(b1, H_DIM, D_DIM, half);
    quantum_kernel<<<gQ, QWARPS * 32, 0, s1>>>(W2, b2, W3, b3, half);
    gemm_resid_ln<<<gF, 512, SM_TOT2, s1>>>(b4, x, gamma, beta, out, half);

    cudaEventRecord(evB, s1);
    cudaStreamWaitEvent(0, evB, 0);
}

// round 16
// speedup vs baseline: 1.0785x; 1.0785x over previous
#include <cuda_runtime.h>
#include <cuda_fp16.h>
#include <cstdint>

#define BATCH   16384
#define D_DIM   768
#define H_DIM   256
#define NQ      8
#define NL      2

// ---------------- scratch -----------------------------------------------------
__device__ float2 g_C[NL][NQ][4];

__device__ __align__(256) float  g_h[BATCH * H_DIM];
__device__ __align__(256) __half g_xf[BATCH * D_DIM];
__device__ __align__(256) __half g_w1f[D_DIM * H_DIM];
__device__ __align__(256) __half g_w4f[H_DIM * D_DIM];
__device__ __align__(256) __half g_ef[BATCH * H_DIM];

// ---------------- helpers ------------------------------------------------------
__device__ __forceinline__ float2 cmul(float2 a, float2 b) {
    return make_float2(a.x * b.x - a.y * b.y, a.x * b.y + a.y * b.x);
}
__device__ __forceinline__ float2 cadd(float2 a, float2 b) {
    return make_float2(a.x + b.x, a.y + b.y);
}
__device__ __forceinline__ float gelu_exact(float v) {
    return 0.5f * v * (1.0f + erff(v * 0.70710678118654752f));
}
__device__ __forceinline__ uint32_t smem_to_u32(const void* p) {
    uint32_t a;
    asm("{ .reg .u64 t; cvta.to.shared.u64 t, %1; cvt.u32.u64 %0, t; }"
        : "=r"(a) : "l"(p));
    return a;
}
__device__ __forceinline__ uint2 cvt4_f16(float4 v) {
    __half2 p0 = __floats2half2_rn(v.x, v.y);
    __half2 p1 = __floats2half2_rn(v.z, v.w);
    uint2 o;
    o.x = *reinterpret_cast<uint32_t*>(&p0);
    o.y = *reinterpret_cast<uint32_t*>(&p1);
    return o;
}
__device__ __forceinline__ float2 shfl2(float2 v, int mask) {
    v.x = __shfl_xor_sync(0xffffffffu, v.x, mask);
    v.y = __shfl_xor_sync(0xffffffffu, v.y, mask);
    return v;
}

__device__ __forceinline__ void ldsm_x4(uint32_t addr, uint32_t* r) {
    asm volatile("ldmatrix.sync.aligned.m8n8.x4.shared.b16 {%0,%1,%2,%3}, [%4];"
        : "=r"(r[0]), "=r"(r[1]), "=r"(r[2]), "=r"(r[3]) : "r"(addr));
}
__device__ __forceinline__ void ldsm_x4t(uint32_t addr, uint32_t* r) {
    asm volatile("ldmatrix.sync.aligned.m8n8.x4.trans.shared.b16 {%0,%1,%2,%3}, [%4];"
        : "=r"(r[0]), "=r"(r[1]), "=r"(r[2]), "=r"(r[3]) : "r"(addr));
}
__device__ __forceinline__ void mma16816(float* d, const uint32_t* a,
                                         uint32_t b0, uint32_t b1) {
    asm volatile(
        "mma.sync.aligned.m16n8k16.row.col.f32.f16.f16.f32 "
        "{%0,%1,%2,%3}, {%4,%5,%6,%7}, {%8,%9}, {%0,%1,%2,%3};"
        : "+f"(d[0]), "+f"(d[1]), "+f"(d[2]), "+f"(d[3])
        : "r"(a[0]), "r"(a[1]), "r"(a[2]), "r"(a[3]), "r"(b0), "r"(b1));
}
__device__ __forceinline__ void cp16(uint32_t saddr, const void* g) {
    asm volatile("cp.async.cg.shared.global [%0], [%1], 16;"
        :: "r"(saddr), "l"(g) : "memory");
}
#define CP_COMMIT() asm volatile("cp.async.commit_group;" ::: "memory")
#define CP_WAIT(n)  asm volatile("cp.async.wait_group %0;" :: "n"(n) : "memory")

// ---------------- prep_all: gates + weight conv + x conv, ONE launch ---------
#define XB  ((BATCH * D_DIM / 4 + 255) / 256)           // 12288
#define WB  ((2 * (D_DIM * H_DIM / 4) + 255) / 256)     // 384

__global__ __launch_bounds__(256) void prep_all(
    const float* __restrict__ qw,
    const float4* __restrict__ x4,
    const float4* __restrict__ w14, const float4* __restrict__ w44,
    uint2* __restrict__ xf, uint2* __restrict__ w1f, uint2* __restrict__ w4f)
{
    int b = blockIdx.x;
    int tid = threadIdx.x;
    if (b == 0) {
        if (tid >= NL * NQ) return;
        int l = tid / NQ, i = tid % NQ;
        float w0 = qw[(l * NQ + i) * 3 + 0];
        float w1 = qw[(l * NQ + i) * 3 + 1];
        float w2 = qw[(l * NQ + i) * 3 + 2];
        float c0 = cosf(0.5f * w0), s0 = sinf(0.5f * w0);
        float c1 = cosf(0.5f * w1), s1 = sinf(0.5f * w1);
        float c2 = cosf(0.5f * w2), s2 = sinf(0.5f * w2);
        float2 e0  = make_float2(c0, -s0);
        float2 e0c = make_float2(c0,  s0);
        float2 T00 = make_float2( c1 * e0.x,   c1 * e0.y);
        float2 T01 = make_float2(-s1 * e0c.x, -s1 * e0c.y);
        float2 T10 = make_float2( s1 * e0.x,   s1 * e0.y);
        float2 T11 = make_float2( c1 * e0c.x,  c1 * e0c.y);
        float2 e2  = make_float2(c2, -s2);
        float2 e2c = make_float2(c2,  s2);
        g_C[l][i][0] = cmul(e2,  T00);
        g_C[l][i][1] = cmul(e2,  T01);
        g_C[l][i][2] = cmul(e2c, T10);
        g_C[l][i][3] = cmul(e2c, T11);
    } else if (b <= WB) {
        int i = (b - 1) * 256 + tid;
        int nw4 = D_DIM * H_DIM / 4;
        if (i >= 2 * nw4) return;
        if (i < nw4) w1f[i] = cvt4_f16(w14[i]);
        else         w4f[i - nw4] = cvt4_f16(w44[i - nw4]);
    } else {
        int i = (b - 1 - WB) * 256 + tid;
        if (i >= BATCH * D_DIM / 4) return;
        xf[i] = cvt4_f16(x4[i]);
    }
}

// ---------------- GEMM-1: h = gelu(x@W1+b1), fp16 MMA, 4-stage ---------------
#define STAGES 4
#define STAGE_BYTES 16384
#define SM_TOT (STAGES * STAGE_BYTES)

__global__ __launch_bounds__(256, 2) void gemm_gelu(
    const float* __restrict__ bias, int N, int K, int brow0)
{
    extern __shared__ char smem[];
    const __half* Af = g_xf;
    const __half* Bf = g_w1f;
    float* Cout = g_h;

    uint32_t sb = smem_to_u32(smem);
    int t = threadIdx.x, wid = t >> 5, lane = t & 31;
    int brow = brow0 + blockIdx.y * 128, bcol = blockIdx.x * 128;
    int warpM = (wid & 3) * 32, warpN = (wid >> 2) * 64;
    int grp = lane >> 2, qc = lane & 3;

    float acc[2][8][4];
#pragma unroll
    for (int i = 0; i < 2; ++i)
#pragma unroll
        for (int j = 0; j < 8; ++j)
#pragma unroll
            for (int k = 0; k < 4; ++k) acc[i][j][k] = 0.f;

    int NC = K / 32;
    int a_row0 = t >> 2, a_kseg = t & 3;
    int b_kr0  = t >> 4, b_nseg = t & 15;

    uint32_t aoff[2], boff[4];
#pragma unroll
    for (int mf = 0; mf < 2; ++mf) {
        int m = warpM + mf * 16 + (lane & 15);
        aoff[mf] = (uint32_t)((m * 64 + (lane >> 4) * 16) ^ ((m & 7) << 4));
    }
#pragma unroll
    for (int n16 = 0; n16 < 4; ++n16) {
        uint32_t nb = (uint32_t)(warpN + n16 * 16 + (lane >> 4) * 8) * 2;
        boff[n16] = (uint32_t)((lane & 15) * 256) + (nb ^ (uint32_t)((lane & 7) << 4));
    }

    auto issue_stage = [&](int ck, int stg) {
        uint32_t base = sb + stg * STAGE_BYTES;
        int k0 = ck * 32;
#pragma unroll
        for (int i = 0; i < 2; ++i) {
            int row = a_row0 + i * 64;
            uint32_t off = (uint32_t)((row * 64 + a_kseg * 16) ^ ((row & 7) << 4));
            cp16(base + off, Af + (size_t)(brow + row) * K + k0 + a_kseg * 8);
        }
#pragma unroll
        for (int i = 0; i < 2; ++i) {
            int kr = b_kr0 + i * 16;
            uint32_t off = (uint32_t)((kr * 256 + b_nseg * 16) ^ ((kr & 7) << 4));
            cp16(base + 8192 + off, Bf + (size_t)(k0 + kr) * N + bcol + b_nseg * 8);
        }
    };

#pragma unroll
    for (int p = 0; p < STAGES - 1; ++p) {
        if (p < NC) issue_stage(p, p);
        CP_COMMIT();
    }

    for (int ck = 0; ck < NC; ++ck) {
        CP_WAIT(STAGES - 2);
        __syncthreads();

        int nx = ck + STAGES - 1;
        if (nx < NC) issue_stage(nx, nx % STAGES);
        CP_COMMIT();

        uint32_t base = sb + (uint32_t)((ck % STAGES) * STAGE_BYTES);
        uint32_t bbase = base + 8192;

#pragma unroll
        for (int s = 0; s < 2; ++s) {
            uint32_t sa = (uint32_t)(s << 5);
            uint32_t sbo = (uint32_t)(s * 4096);
            uint32_t ah[2][4];
#pragma unroll
            for (int mf = 0; mf < 2; ++mf)
                ldsm_x4(base + (aoff[mf] ^ sa), ah[mf]);
#pragma unroll
            for (int n16 = 0; n16 < 4; ++n16) {
                uint32_t bh[4];
                ldsm_x4t(bbase + boff[n16] + sbo, bh);
#pragma unroll
                for (int half = 0; half < 2; ++half) {
                    int nf = n16 * 2 + half;
#pragma unroll
                    for (int mf = 0; mf < 2; ++mf)
                        mma16816(acc[mf][nf], ah[mf], bh[half * 2], bh[half * 2 + 1]);
                }
            }
        }
    }

#pragma unroll
    for (int mf = 0; mf < 2; ++mf) {
        int r0 = brow + warpM + mf * 16 + grp;
#pragma unroll
        for (int nf = 0; nf < 8; ++nf) {
            int col = bcol + warpN + nf * 8 + qc * 2;
            float bv0 = bias[col], bv1 = bias[col + 1];
            float v0 = gelu_exact(acc[mf][nf][0] + bv0);
            float v1 = gelu_exact(acc[mf][nf][1] + bv1);
            float v2 = gelu_exact(acc[mf][nf][2] + bv0);
            float v3 = gelu_exact(acc[mf][nf][3] + bv1);
            size_t o0 = (size_t)r0 * N + col;
            size_t o1 = o0 + (size_t)8 * N;
            *(float2*)(Cout + o0) = make_float2(v0, v1);
            *(float2*)(Cout + o1) = make_float2(v2, v3);
        }
    }
}

// ---------------- GEMM-2 fused: out = LN(x + e@W4 + b4), coalesced epi -------
#define LSTAGES 3
#define LA_BYTES 2048
#define LB_BYTES 49152
#define LSTAGE_BYTES (LA_BYTES + LB_BYTES)
#define SM_TOT2 (LSTAGES * LSTAGE_BYTES)    // 153600 >= 98304 staging

__global__ __launch_bounds__(512, 1) void gemm_resid_ln(
    const float* __restrict__ bias, const float* __restrict__ resid,
    const float* __restrict__ gamma, const float* __restrict__ beta,
    float* __restrict__ out, int row0)
{
    extern __shared__ char smem[];
    const __half* Af = g_ef;
    const __half* Bf = g_w4f;
    const int N = D_DIM, K = H_DIM;

    uint32_t sb = smem_to_u32(smem);
    int t = threadIdx.x, wid = t >> 5, lane = t & 31;
    int brow = row0 + blockIdx.x * 32;
    int grp = lane >> 2, qc = lane & 3;

    float acc[2][6][4];
#pragma unroll
    for (int i = 0; i < 2; ++i)
#pragma unroll
        for (int j = 0; j < 6; ++j)
#pragma unroll
            for (int k = 0; k < 4; ++k) acc[i][j][k] = 0.f;

    const int NC = K / 32;

    int a_row = t >> 2, a_kseg = t & 3;
    int b_kr = t >> 4, b_nc0 = t & 15;

    uint32_t aoff[2], boff[3];
#pragma unroll
    for (int mf = 0; mf < 2; ++mf) {
        int m = mf * 16 + (lane & 15);
        aoff[mf] = (uint32_t)((m * 64 + (lane >> 4) * 16) ^ ((m & 7) << 4));
    }
#pragma unroll
    for (int n16 = 0; n16 < 3; ++n16) {
        uint32_t nb = (uint32_t)(wid * 48 + n16 * 16 + (lane >> 4) * 8) * 2;
        boff[n16] = (uint32_t)((lane & 15) * 1536) + (nb ^ (uint32_t)((lane & 7) << 4));
    }

    auto issue_stage = [&](int ck, int stg) {
        uint32_t base = sb + stg * LSTAGE_BYTES;
        int k0 = ck * 32;
        if (t < 128) {
            uint32_t off = (uint32_t)((a_row * 64 + a_kseg * 16) ^ ((a_row & 7) << 4));
            cp16(base + off, Af + (size_t)(brow + a_row) * K + k0 + a_kseg * 8);
        }
        uint32_t bb = base + LA_BYTES;
#pragma unroll
        for (int i = 0; i < 6; ++i) {
            int nc = b_nc0 + i * 16;
            uint32_t off = (uint32_t)(b_kr * 1536 + ((nc * 16) ^ ((b_kr & 7) << 4)));
            cp16(bb + off, Bf + (size_t)(k0 + b_kr) * N + nc * 8);
        }
    };

#pragma unroll
    for (int p = 0; p < LSTAGES - 1; ++p) {
        if (p < NC) issue_stage(p, p);
        CP_COMMIT();
    }

    for (int ck = 0; ck < NC; ++ck) {
        CP_WAIT(LSTAGES - 2);
        __syncthreads();

        int nx = ck + LSTAGES - 1;
        if (nx < NC) issue_stage(nx, nx % LSTAGES);
        CP_COMMIT();

        uint32_t base = sb + (uint32_t)((ck % LSTAGES) * LSTAGE_BYTES);
        uint32_t bbase = base + LA_BYTES;

#pragma unroll
        for (int s = 0; s < 2; ++s) {
            uint32_t sa = (uint32_t)(s << 5);
            uint32_t sbo = (uint32_t)(s * 16 * 1536);
            uint32_t ah[2][4];
#pragma unroll
            for (int mf = 0; mf < 2; ++mf)
                ldsm_x4(base + (aoff[mf] ^ sa), ah[mf]);
#pragma unroll
            for (int n16 = 0; n16 < 3; ++n16) {
                uint32_t bh[4];
                ldsm_x4t(bbase + boff[n16] + sbo, bh);
#pragma unroll
                for (int half = 0; half < 2; ++half) {
                    int nf = n16 * 2 + half;
#pragma unroll
                    for (int mf = 0; mf < 2; ++mf)
                        mma16816(acc[mf][nf], ah[mf], bh[half * 2], bh[half * 2 + 1]);
                }
            }
        }
    }

    // ---- epilogue: stage acc+bias to smem, then per-row coalesced LN ----
    CP_WAIT(0);
    __syncthreads();
    float* ys = (float*)smem;    // [32][768] fp32 = 96 KB

#pragma unroll
    for (int mf = 0; mf < 2; ++mf) {
        int r0 = mf * 16 + grp;
#pragma unroll
        for (int nf = 0; nf < 6; ++nf) {
            int col = wid * 48 + nf * 8 + qc * 2;
            float2 bv = *(const float2*)(bias + col);
            ys[r0 * D_DIM + col]           = acc[mf][nf][0] + bv.x;
            ys[r0 * D_DIM + col + 1]       = acc[mf][nf][1] + bv.y;
            ys[(r0 + 8) * D_DIM + col]     = acc[mf][nf][2] + bv.x;
            ys[(r0 + 8) * D_DIM + col + 1] = acc[mf][nf][3] + bv.y;
        }
    }
    __syncthreads();

#pragma unroll
    for (int rr = 0; rr < 2; ++rr) {
        int lrow = wid * 2 + rr;
        size_t grow = (size_t)(brow + lrow) * D_DIM;
        float y[24];
        float sum = 0.f, sq = 0.f;
#pragma unroll
        for (int i = 0; i < 6; ++i) {
            int col = lane * 4 + i * 128;
            float4 s4 = *(const float4*)(ys + lrow * D_DIM + col);
            float4 r4 = *(const float4*)(resid + grow + col);
            float y0 = s4.x + r4.x, y1 = s4.y + r4.y;
            float y2 = s4.z + r4.z, y3 = s4.w + r4.w;
            y[4 * i + 0] = y0; y[4 * i + 1] = y1;
            y[4 * i + 2] = y2; y[4 * i + 3] = y3;
            sum += y0 + y1 + y2 + y3;
            sq  += y0 * y0 + y1 * y1 + y2 * y2 + y3 * y3;
        }
#pragma unroll
        for (int o = 16; o; o >>= 1) {
            sum += __shfl_xor_sync(0xffffffffu, sum, o);
            sq  += __shfl_xor_sync(0xffffffffu, sq,  o);
        }
        float mu  = sum * (1.0f / D_DIM);
        float var = sq * (1.0f / D_DIM) - mu * mu;
        float inv = rsqrtf(var + 1e-5f);
#pragma unroll
        for (int i = 0; i < 6; ++i) {
            int col = lane * 4 + i * 128;
            float4 gm = *(const float4*)(gamma + col);
            float4 bt = *(const float4*)(beta + col);
            float4 o4;
            o4.x = gm.x * (y[4 * i + 0] - mu) * inv + bt.x;
            o4.y = gm.y * (y[4 * i + 1] - mu) * inv + bt.y;
            o4.z = gm.z * (y[4 * i + 2] - mu) * inv + bt.z;
            o4.w = gm.w * (y[4 * i + 3] - mu) * inv + bt.w;
            *(float4*)(out + grow + col) = o4;
        }
    }
}

// ---------------- quantum bottleneck ------------------------------------------
template <int M_, int H_>
__device__ __forceinline__ void apply_gate(float2* amp, int lane,
    const float2* Cw, float c, float s)
{
    float2 C00 = Cw[0], C01 = Cw[1], C10 = Cw[2], C11 = Cw[3];
    float2 U00 = make_float2(C00.x * c + C01.x * s, C00.y * c + C01.y * s);
    float2 U01 = make_float2(C01.x * c - C00.x * s, C01.y * c - C00.y * s);
    float2 U10 = make_float2(C10.x * c + C11.x * s, C10.y * c + C11.y * s);
    float2 U11 = make_float2(C11.x * c - C10.x * s, C11.y * c - C10.y * s);

    constexpr int mreg  = (M_ >> 5) & 7;
    constexpr int mlane = M_ & 31;
    constexpr int hreg  = (H_ >> 5) & 7;
    constexpr int hlane = H_ & 31;
    bool lp = (__popc(lane & hlane) & 1) != 0;
    if (mreg == 0) {
#pragma unroll
        for (int r = 0; r < 8; ++r) {
            bool hi = lp ^ ((__popc(r & hreg) & 1) != 0);
            float2 o = shfl2(amp[r], mlane);
            float2 lo_v = cadd(cmul(U00, amp[r]), cmul(U01, o));
            float2 hi_v = cadd(cmul(U10, o), cmul(U11, amp[r]));
            amp[r] = hi ? hi_v : lo_v;
        }
    } else {
#pragma unroll
        for (int r = 0; r < 8; ++r) {
            int pr = r ^ mreg;
            if (r < pr) {
                float2 a = amp[r], b = amp[pr];
                float2 ash = (mlane != 0) ? shfl2(a, mlane) : a;
                float2 bsh = (mlane != 0) ? shfl2(b, mlane) : b;
                bool hi_r  = lp ^ ((__popc(r  & hreg) & 1) != 0);
                bool hi_pr = lp ^ ((__popc(pr & hreg) & 1) != 0);
                amp[r]  = hi_r  ? cadd(cmul(U10, bsh), cmul(U11, a))
                                : cadd(cmul(U00, a),   cmul(U01, bsh));
                amp[pr] = hi_pr ? cadd(cmul(U10, ash), cmul(U11, b))
                                : cadd(cmul(U00, b),   cmul(U01, ash));
            }
        }
    }
}

#define QWARPS 8
__global__ __launch_bounds__(QWARPS * 32) void quantum_kernel(
    const float* __restrict__ W2, const float* __restrict__ b2,
    const float* __restrict__ W3, const float* __restrict__ b3,
    int row0)
{
    int warp = threadIdx.x >> 5;
    int lane = threadIdx.x & 31;
    int row  = row0 + blockIdx.x * QWARPS + warp;

    const float* hrow = g_h + (size_t)row * H_DIM;
    float fj[8] = {0, 0, 0, 0, 0, 0, 0, 0};
#pragma unroll
    for (int m = 0; m < 8; ++m) {
        int k = lane + 32 * m;
        float hv = hrow[k];
        const float4* w2p = (const float4*)(W2 + (size_t)k * 8);
        float4 wa = w2p[0], wb = w2p[1];
        fj[0] += hv * wa.x; fj[1] += hv * wa.y;
        fj[2] += hv * wa.z; fj[3] += hv * wa.w;
        fj[4] += hv * wb.x; fj[5] += hv * wb.y;
        fj[6] += hv * wb.z; fj[7] += hv * wb.w;
    }
#pragma unroll
    for (int j = 0; j < 8; ++j)
#pragma unroll
        for (int o = 16; o; o >>= 1)
            fj[j] += __shfl_xor_sync(0xffffffffu, fj[j], o);

    float cf[8], sf[8];
#pragma unroll
    for (int j = 0; j < 8; ++j) {
        float f = 0.5f * (fj[j] + b2[j]);
        sincosf(f, &sf[j], &cf[j]);
    }

    auto vsel = [&](int w, bool b) -> float2 {
        float2 Ca = g_C[0][w][b ? 2 : 0];
        float2 Cb = g_C[0][w][b ? 3 : 1];
        return make_float2(Ca.x * cf[w] + Cb.x * sf[w], Ca.y * cf[w] + Cb.y * sf[w]);
    };
    float2 pl = vsel(3, (lane & 16) != 0);
    pl = cmul(pl, vsel(4, (lane & 8) != 0));
    pl = cmul(pl, vsel(5, (lane & 4) != 0));
    pl = cmul(pl, vsel(6, (lane & 2) != 0));
    pl = cmul(pl, vsel(7, (lane & 1) != 0));

    float2 amp[8];
    {
        float2 a0 = vsel(0, false), a1 = vsel(0, true);
        float2 b0 = vsel(1, false), b1 = vsel(1, true);
        float2 c0 = vsel(2, false), c1 = vsel(2, true);
        float2 p00 = cmul(a0, b0), p01v = cmul(a0, b1);
        float2 p10 = cmul(a1, b0), p11 = cmul(a1, b1);
        amp[0] = cmul(cmul(p00, c0), pl);
        amp[1] = cmul(cmul(p00, c1), pl);
        amp[2] = cmul(cmul(p01v, c0), pl);
        amp[3] = cmul(cmul(p01v, c1), pl);
        amp[4] = cmul(cmul(p10, c0), pl);
        amp[5] = cmul(cmul(p10, c1), pl);
        amp[6] = cmul(cmul(p11, c0), pl);
        amp[7] = cmul(cmul(p11, c1), pl);
    }

    apply_gate<0xC0, 0x7F>(amp, lane, g_C[1][0], cf[0], sf[0]);
    apply_gate<0x60, 0xC0>(amp, lane, g_C[1][1], cf[1], sf[1]);
    apply_gate<0x30, 0xE0>(amp, lane, g_C[1][2], cf[2], sf[2]);
    apply_gate<0x18, 0xF0>(amp, lane, g_C[1][3], cf[3], sf[3]);
    apply_gate<0x0C, 0xF8>(amp, lane, g_C[1][4], cf[4], sf[4]);
    apply_gate<0x06, 0xFC>(amp, lane, g_C[1][5], cf[5], sf[5]);
    apply_gate<0x03, 0xFE>(amp, lane, g_C[1][6], cf[6], sf[6]);
    apply_gate<0xC1, 0xFF>(amp, lane, g_C[1][7], cf[7], sf[7]);

    // ---- factored measurement ----
    // zf[i] = lanesign_i * S_{mreg_i};  mreg in {6,5,2}; lane masks per wire:
    //   wire: 0:D5 (m=6,l=0x15) 1:BF (5,0x1F) 2:5F (2,0x1F) 3:AF (5,0x0F)
    //         4:57 (2,0x17) 5:AB (5,0x0B) 6:55 (2,0x15) 7:AA (5,0x0A)
    float p[8];
#pragma unroll
    for (int r = 0; r < 8; ++r)
        p[r] = amp[r].x * amp[r].x + amp[r].y * amp[r].y;
    // S_m = sum_r sign(popc(r&m)) * p[r]
    float S6 = p[0] + p[1] - p[2] - p[3] - p[4] - p[5] + p[6] + p[7];
    float S5 = p[0] - p[1] + p[2] - p[3] - p[4] + p[5] - p[6] + p[7];
    float S2 = p[0] + p[1] - p[2] - p[3] + p[4] + p[5] - p[6] - p[7];

    const int lmask[8] = {0x15, 0x1F, 0x1F, 0x0F, 0x17, 0x0B, 0x15, 0x0A};
    float zf[8];
    zf[0] = (__popc(lane & lmask[0]) & 1) ? -S6 : S6;
    zf[1] = (__popc(lane & lmask[1]) & 1) ? -S5 : S5;
    zf[2] = (__popc(lane & lmask[2]) & 1) ? -S2 : S2;
    zf[3] = (__popc(lane & lmask[3]) & 1) ? -S5 : S5;
    zf[4] = (__popc(lane & lmask[4]) & 1) ? -S2 : S2;
    zf[5] = (__popc(lane & lmask[5]) & 1) ? -S5 : S5;
    zf[6] = (__popc(lane & lmask[6]) & 1) ? -S2 : S2;
    zf[7] = (__popc(lane & lmask[7]) & 1) ? -S5 : S5;

#pragma unroll
    for (int j = 0; j < 8; ++j)
#pragma unroll
        for (int o = 16; o; o >>= 1)
            zf[j] += __shfl_xor_sync(0xffffffffu, zf[j], o);

    size_t ebase = (size_t)row * H_DIM;
#pragma unroll
    for (int m = 0; m < 8; ++m) {
        int k = lane + 32 * m;
        float acc = b3[k];
#pragma unroll
        for (int j = 0; j < 8; ++j) acc += zf[j] * W3[j * H_DIM + k];
        g_ef[ebase + k] = __float2half(gelu_exact(acc));
    }
}

// ---------------- launch ------------------------------------------------------
extern "C" void kernel_launch(void* const* d_in, const int* in_sizes, int n_in,
                              void* d_out, int out_size) {
    const float* x     = (const float*)d_in[0];
    const float* W1    = (const float*)d_in[1];
    const float* b1    = (const float*)d_in[2];
    const float* W2    = (const float*)d_in[3];
    const float* b2    = (const float*)d_in[4];
    const float* qw    = (const float*)d_in[5];
    const float* W3    = (const float*)d_in[6];
    const float* b3    = (const float*)d_in[7];
    const float* W4    = (const float*)d_in[8];
    const float* b4    = (const float*)d_in[9];
    const float* gamma = (const float*)d_in[10];
    const float* beta  = (const float*)d_in[11];
    float* out = (float*)d_out;

    int Brows = in_sizes[0] / D_DIM;   // 16384
    int half  = Brows / 2;

    static cudaStream_t s1 = nullptr;
    static cudaEvent_t evP = nullptr, evB = nullptr;
    if (!s1) {
        cudaStreamCreateWithFlags(&s1, cudaStreamNonBlocking);
        cudaEventCreateWithFlags(&evP, cudaEventDisableTiming);
        cudaEventCreateWithFlags(&evB, cudaEventDisableTiming);
        cudaFuncSetAttribute(gemm_gelu, cudaFuncAttributeMaxDynamicSharedMemorySize, SM_TOT);
        cudaFuncSetAttribute(gemm_resid_ln, cudaFuncAttributeMaxDynamicSharedMemorySize, SM_TOT2);
    }

    void *pxf, *pw1f, *pw4f;
    cudaGetSymbolAddress(&pxf, g_xf);
    cudaGetSymbolAddress(&pw1f, g_w1f);
    cudaGetSymbolAddress(&pw4f, g_w4f);

    prep_all<<<1 + WB + XB, 256>>>(
        qw, (const float4*)x, (const float4*)W1, (const float4*)W4,
        (uint2*)pxf, (uint2*)pw1f, (uint2*)pw4f);

    cudaEventRecord(evP, 0);
    cudaStreamWaitEvent(s1, evP, 0);

    dim3 gG(H_DIM / 128, half / 128);   // (2, 64) per half
    int  gQ = half / QWARPS;            // 1024
    int  gF = half / 32;                // 256

    // chain A (rows [0, half)) on default stream
    gemm_gelu<<<gG, 256, SM_TOT>>>(b1, H_DIM, D_DIM, 0);
    quantum_kernel<<<gQ, QWARPS * 32>>>(W2, b2, W3, b3, 0);
    gemm_resid_ln<<<gF, 512, SM_TOT2>>>(b4, x, gamma, beta, out, 0);

    // chain B (rows [half, Brows)) on s1
    gemm_gelu<<<gG, 256, SM_TOT, s1>>>(b1, H_DIM, D_DIM, half);
    quantum_kernel<<<gQ, QWARPS * 32, 0, s1>>>(W2, b2, W3, b3, half);
    gemm_resid_ln<<<gF, 512, SM_TOT2, s1>>>(b4, x, gamma, beta, out, half);

    cudaEventRecord(evB, s1);
    cudaStreamWaitEvent(0, evB, 0);
}